// round 15
// baseline (speedup 1.0000x reference)
#include <cuda_runtime.h>
#include <cstdint>

#define NUM_JOINT 19
#define ROOT_SCALE 200.0f
#define BLOCK 32
#define TILE_FLOATS (BLOCK * NUM_JOINT * 4)   // 2432
#define TILE_BYTES  (TILE_FLOATS * 4)         // 9728
#define GRID (148 * 7)                         // 1036: every SM exactly 7 CTAs

__device__ __forceinline__ void tma_load(uint32_t sdst, const float* gsrc, uint32_t mb) {
    asm volatile("mbarrier.arrive.expect_tx.shared.b64 _, [%0], %1;"
                 :: "r"(mb), "r"((uint32_t)TILE_BYTES) : "memory");
    asm volatile("cp.async.bulk.shared::cta.global.mbarrier::complete_tx::bytes "
                 "[%0], [%1], %2, [%3];"
                 :: "r"(sdst), "l"(gsrc), "r"((uint32_t)TILE_BYTES), "r"(mb) : "memory");
}

__global__ __launch_bounds__(BLOCK, 7)
void fk_kernel(const float* __restrict__ root,
               const float* __restrict__ joint,
               const float* __restrict__ offsets,
               float* __restrict__ out,
               int ntiles)
{
    // s[0], s[1]: depth-2 load ring.  s[2]: dedicated store staging.
    __shared__ alignas(16) float s[3][TILE_FLOATS];        // 29184 B
    __shared__ alignas(8)  unsigned long long mbar[2];

    const int t = threadIdx.x;
    const uint32_t s0 = (uint32_t)__cvta_generic_to_shared(&s[0][0]);
    const uint32_t ss = (uint32_t)__cvta_generic_to_shared(&s[2][0]);
    const uint32_t m0 = (uint32_t)__cvta_generic_to_shared(&mbar[0]);

    if (t == 0) {
        asm volatile("mbarrier.init.shared.b64 [%0], 1;" :: "r"(m0)     : "memory");
        asm volatile("mbarrier.init.shared.b64 [%0], 1;" :: "r"(m0 + 8) : "memory");
    }
    __syncwarp();

    const int parents[NUM_JOINT] = {-1,0,1,2,3,2,5,6,7,2,9,10,11,0,13,14,0,16,17};

    // Translations -> registers once per persistent CTA (uniform LDG broadcast).
    float tox[NUM_JOINT], toy[NUM_JOINT], toz[NUM_JOINT];
    #pragma unroll
    for (int j = 0; j < NUM_JOINT; j++) {
        tox[j] = __ldg(&offsets[j * 16 + 3]);
        toy[j] = __ldg(&offsets[j * 16 + 7]);
        toz[j] = __ldg(&offsets[j * 16 + 11]);
    }

    // Prologue: depth-2 prefetch of tiles it=0,1 into load ring bufs 0,1.
    if (t == 0) {
        if (blockIdx.x < ntiles)
            tma_load(s0, joint + (size_t)blockIdx.x * TILE_FLOATS, m0);
        if (blockIdx.x + GRID < ntiles)
            tma_load(s0 + TILE_BYTES,
                     joint + (size_t)(blockIdx.x + GRID) * TILE_FLOATS, m0 + 8);
    }

    int it = 0;
    for (int tile = blockIdx.x; tile < ntiles; tile += GRID, it++) {
        const int buf = it & 1;
        const uint32_t parity = (uint32_t)((it >> 1) & 1);

        // Root fetch overlaps the load-wait window.
        const long long b = (long long)tile * BLOCK + t;
        const float rx = __ldg(&root[b * 3 + 0]) * ROOT_SCALE;
        const float ry = __ldg(&root[b * 3 + 1]) * ROOT_SCALE;
        const float rz = __ldg(&root[b * 3 + 2]) * ROOT_SCALE;

        // Wait for this tile (its load was issued two iterations ago).
        asm volatile(
            "{\n\t.reg .pred P;\n\t"
            "W%=:\n\t"
            "mbarrier.try_wait.parity.acquire.cta.shared::cta.b64 P, [%0], %1, 0x989680;\n\t"
            "@!P bra W%=;\n\t}"
            :: "r"(m0 + buf * 8), "r"(parity) : "memory");

        // Slurp all 19 quats into registers; frees this ring buffer immediately.
        const float* row = &s[buf][t * (NUM_JOINT * 4)];   // 76-float stride: conflict-free
        float4 q[NUM_JOINT];
        #pragma unroll
        for (int j = 0; j < NUM_JOINT; j++)
            q[j] = *(const float4*)&row[j * 4];
        __syncwarp();

        // Depth-2 prefetch into the just-freed buffer. NO store-drain dependency:
        // loads and stores are fully decoupled streams.
        if (t == 0 && tile + 2 * GRID < ntiles) {
            asm volatile("fence.proxy.async.shared::cta;" ::: "memory");
            tma_load(s0 + buf * TILE_BYTES,
                     joint + (size_t)(tile + 2 * GRID) * TILE_FLOATS, m0 + buf * 8);
        }

        // ---- FK chain via composite (non-unit) quaternions, in registers ----
        float gw[NUM_JOINT], gx[NUM_JOINT], gy[NUM_JOINT], gz[NUM_JOINT];
        float ox[NUM_JOINT], oy[NUM_JOINT], oz[NUM_JOINT];
        #pragma unroll
        for (int j = 0; j < NUM_JOINT; j++) {
            float aw, ax, ay, az;
            if (j == 0) {
                aw = q[0].x; ax = q[0].y; ay = q[0].z; az = q[0].w;
            } else {
                const int p = parents[j];
                const float bw = q[j].x, bx = q[j].y, by = q[j].z, bz = q[j].w;
                aw = gw[p]*bw - gx[p]*bx - gy[p]*by - gz[p]*bz;
                ax = gw[p]*bx + gx[p]*bw + gy[p]*bz - gz[p]*by;
                ay = gw[p]*by - gx[p]*bz + gy[p]*bw + gz[p]*bx;
                az = gw[p]*bz + gx[p]*by - gy[p]*bx + gz[p]*bw;
            }
            gw[j] = aw; gx[j] = ax; gy[j] = ay; gz[j] = az;

            const float tx = tox[j], ty = toy[j], tz = toz[j];

            const float n  = aw*aw + ax*ax + ay*ay + az*az;
            const float sc = __fdividef(2.0f, n);

            const float cx = ay*tz - az*ty;
            const float cy = az*tx - ax*tz;
            const float cz = ax*ty - ay*tx;

            const float dx = aw*cx + (ay*cz - az*cy);
            const float dy = aw*cy + (az*cx - ax*cz);
            const float dz = aw*cz + (ax*cy - ay*cx);

            float vx = tx + sc * dx;
            float vy = ty + sc * dy;
            float vz = tz + sc * dz;
            if (j > 0) {
                const int p = parents[j];
                vx += ox[p]; vy += oy[p]; vz += oz[p];
            }
            ox[j] = vx; oy[j] = vy; oz[j] = vz;
        }

        // Previous store had a full compute phase to drain -> near-zero stall here.
        if (t == 0)
            asm volatile("cp.async.bulk.wait_group 0;" ::: "memory");
        __syncwarp();

        // Stage results in the dedicated store buffer and commit the bulk store.
        float* wrow = &s[2][t * (NUM_JOINT * 4)];
        #pragma unroll
        for (int j = 0; j < NUM_JOINT; j++) {
            float4 o;
            o.x = ox[j] + rx; o.y = oy[j] + ry; o.z = oz[j] + rz; o.w = 1.0f;
            *(float4*)&wrow[j * 4] = o;
        }
        __syncwarp();

        if (t == 0) {
            asm volatile("fence.proxy.async.shared::cta;" ::: "memory");
            float* gdst = out + (size_t)tile * TILE_FLOATS;
            asm volatile("cp.async.bulk.global.shared::cta.bulk_group [%0], [%1], %2;"
                         :: "l"(gdst), "r"(ss), "r"((uint32_t)TILE_BYTES) : "memory");
            asm volatile("cp.async.bulk.commit_group;" ::: "memory");
        }
    }

    // smem must outlive the final store.
    if (t == 0)
        asm volatile("cp.async.bulk.wait_group 0;" ::: "memory");
}

extern "C" void kernel_launch(void* const* d_in, const int* in_sizes, int n_in,
                              void* d_out, int out_size)
{
    const float* root    = (const float*)d_in[0];   // (B, 3)
    const float* joint   = (const float*)d_in[1];   // (B, 76)
    const float* offsets = (const float*)d_in[2];   // (19, 4, 4)
    float* out = (float*)d_out;                     // (B, 19, 4)

    const int B = in_sizes[1] / (NUM_JOINT * 4);    // 262144
    const int ntiles = B / BLOCK;                   // 8192
    fk_kernel<<<GRID, BLOCK>>>(root, joint, offsets, out, ntiles);
}